// round 1
// baseline (speedup 1.0000x reference)
#include <cuda_runtime.h>
#include <math.h>

#define B_   8
#define C1   128
#define C2   256
#define H_   80
#define W_   80
#define P_   (H_ * W_)      // 6400
#define NPT  5
#define KTOT (NPT * C1)     // 640

#define TPIX 64
#define KC   32

// Scratch (device globals; no runtime allocation allowed)
__device__ float  g_wT[KTOT * C2];          // transposed weights [m][c2], m = k*128 + c1
__device__ int4   g_idx[B_ * NPT * P_];     // per (b,k,p): lt, rb, lb, rt flat indices
__device__ float4 g_gw [B_ * NPT * P_];     // per (b,k,p): bilinear weights

// ---------------------------------------------------------------------------
// Kernel 0: transpose cw [C2, C1, NPT] -> g_wT [k*C1 + c1][C2]
// ---------------------------------------------------------------------------
__global__ void wt_kernel(const float* __restrict__ cw) {
    int e = blockIdx.x * 256 + threadIdx.x;
    if (e >= KTOT * C2) return;
    int m  = e / C2;
    int c2 = e % C2;
    int k  = m / C1;
    int c1 = m % C1;
    g_wT[e] = cw[(c2 * C1 + c1) * NPT + k];
}

// ---------------------------------------------------------------------------
// Kernel 1: 3x3 offset conv (pad 1) + bilinear sampling parameters
// One thread per (b, p). 200 blocks x 256 threads.
// ---------------------------------------------------------------------------
__global__ __launch_bounds__(256)
void offset_kernel(const float* __restrict__ x, const float* __restrict__ pw,
                   const float* __restrict__ pb) {
    __shared__ float sw[2 * NPT * C1 * 9];   // 11520 floats = 46 KB
    int t = threadIdx.x;
    for (int i = t; i < 2 * NPT * C1 * 9; i += 256) sw[i] = pw[i];
    __syncthreads();

    int tid = blockIdx.x * 256 + t;
    int b = tid / P_;
    int p = tid % P_;
    int h = p / W_;
    int w = p % W_;

    float acc[2 * NPT];
#pragma unroll
    for (int j = 0; j < 2 * NPT; j++) acc[j] = pb[j];

    int  off[9];
    bool ok[9];
#pragma unroll
    for (int tt = 0; tt < 9; tt++) {
        int dh = tt / 3 - 1, dw = tt % 3 - 1;
        int hh = h + dh, ww = w + dw;
        ok[tt]  = (hh >= 0) && (hh < H_) && (ww >= 0) && (ww < W_);
        off[tt] = hh * W_ + ww;
    }

    const float* xb = x + (size_t)b * C1 * P_;
    for (int c = 0; c < C1; c++) {
        const float* xc = xb + c * P_;
        float v[9];
#pragma unroll
        for (int tt = 0; tt < 9; tt++) v[tt] = ok[tt] ? __ldg(xc + off[tt]) : 0.f;
#pragma unroll
        for (int j = 0; j < 2 * NPT; j++) {
            const float* wj = sw + (j * C1 + c) * 9;
#pragma unroll
            for (int tt = 0; tt < 9; tt++) acc[j] = fmaf(v[tt], wj[tt], acc[j]);
        }
    }

    // base kernel offsets for n=5: pn_x = [0,0,1,1,2], pn_y = [0,1,0,1,0]
    const float pnx[NPT] = {0.f, 0.f, 1.f, 1.f, 2.f};
    const float pny[NPT] = {0.f, 1.f, 0.f, 1.f, 0.f};

#pragma unroll
    for (int k = 0; k < NPT; k++) {
        float px = acc[k]       + (float)h + pnx[k];
        float py = acc[NPT + k] + (float)w + pny[k];
        float pf = floorf(px), qf = floorf(py);
        float xl = fminf(fmaxf(pf,        0.f), (float)(H_ - 1));
        float yl = fminf(fmaxf(qf,        0.f), (float)(W_ - 1));
        float xr = fminf(fmaxf(pf + 1.f,  0.f), (float)(H_ - 1));
        float yr = fminf(fmaxf(qf + 1.f,  0.f), (float)(W_ - 1));
        float pxc = fminf(fmaxf(px, 0.f), (float)(H_ - 1));
        float pyc = fminf(fmaxf(py, 0.f), (float)(W_ - 1));

        float ax = 1.f + xl - pxc;   // (1 + (qx_lt - pxc))
        float bx = 1.f - xr + pxc;   // (1 - (qx_rb - pxc))
        float ay = 1.f + yl - pyc;   // (1 + (qy_lt - pyc))
        float by = 1.f - yr + pyc;   // (1 - (qy_rb - pyc))

        int ixl = (int)xl, iyl = (int)yl, ixr = (int)xr, iyr = (int)yr;
        int gi = (b * NPT + k) * P_ + p;
        g_idx[gi] = make_int4(ixl * W_ + iyl,   // lt
                              ixr * W_ + iyr,   // rb
                              ixl * W_ + iyr,   // lb
                              ixr * W_ + iyl);  // rt
        g_gw[gi] = make_float4(ax * ay, bx * by, ax * by, bx * ay);
    }
}

// ---------------------------------------------------------------------------
// Kernel 2: fused bilinear gather + GEMM (256 x 640 per pixel) + BN + SiLU
// Block: 512 threads, computes C2=256 outputs x TPIX=64 pixels.
// Thread micro-tile: 4 c2 x 8 pixels.
// ---------------------------------------------------------------------------
__global__ __launch_bounds__(512, 2)
void main_kernel(const float* __restrict__ x,
                 const float* __restrict__ bng, const float* __restrict__ bnb,
                 const float* __restrict__ bnm, const float* __restrict__ bnv,
                 float* __restrict__ out) {
    __shared__ float sA[KC][C2];     // weight tile   (32 KB)
    __shared__ float sB[KC][TPIX];   // sampled tile  (8 KB)
    __shared__ int   sGI[4][TPIX];
    __shared__ float sGW[4][TPIX];

    int t  = threadIdx.x;
    int b  = blockIdx.y;
    int p0 = blockIdx.x * TPIX;
    int tc = t & 63;    // c2 group: columns tc*4 .. tc*4+3
    int tp = t >> 6;    // pixel group: pixels tp*8 .. tp*8+7

    const float* xb = x + (size_t)b * C1 * P_;

    float acc[4][8];
#pragma unroll
    for (int j = 0; j < 4; j++)
#pragma unroll
        for (int q = 0; q < 8; q++) acc[j][q] = 0.f;

    for (int kpt = 0; kpt < NPT; kpt++) {
        __syncthreads();
        if (t < TPIX) {
            int gi = (b * NPT + kpt) * P_ + p0 + t;
            int4   id = g_idx[gi];
            float4 gw = g_gw[gi];
            sGI[0][t] = id.x; sGI[1][t] = id.y; sGI[2][t] = id.z; sGI[3][t] = id.w;
            sGW[0][t] = gw.x; sGW[1][t] = gw.y; sGW[2][t] = gw.z; sGW[3][t] = gw.w;
        }
        __syncthreads();

        for (int c10 = 0; c10 < C1; c10 += KC) {
            // Stage sampled tile: 32 c1 x 64 pixels, 4 elems/thread
#pragma unroll
            for (int i = 0; i < 4; i++) {
                int e  = i * 512 + t;
                int kk = e >> 6;
                int pl = e & 63;
                const float* xc = xb + (c10 + kk) * P_;
                sB[kk][pl] = sGW[0][pl] * __ldg(xc + sGI[0][pl])
                           + sGW[1][pl] * __ldg(xc + sGI[1][pl])
                           + sGW[2][pl] * __ldg(xc + sGI[2][pl])
                           + sGW[3][pl] * __ldg(xc + sGI[3][pl]);
            }
            // Stage weight tile: contiguous 8 K floats from g_wT
            {
                const float4* wrow = (const float4*)(g_wT + (kpt * C1 + c10) * C2);
                float4* sAf = (float4*)&sA[0][0];
#pragma unroll
                for (int i = 0; i < 4; i++) sAf[i * 512 + t] = wrow[i * 512 + t];
            }
            __syncthreads();

#pragma unroll
            for (int kk = 0; kk < KC; kk++) {
                float4 a  = *(const float4*)&sA[kk][tc * 4];
                float4 b0 = *(const float4*)&sB[kk][tp * 8];
                float4 b1 = *(const float4*)&sB[kk][tp * 8 + 4];
                acc[0][0] = fmaf(a.x, b0.x, acc[0][0]);
                acc[0][1] = fmaf(a.x, b0.y, acc[0][1]);
                acc[0][2] = fmaf(a.x, b0.z, acc[0][2]);
                acc[0][3] = fmaf(a.x, b0.w, acc[0][3]);
                acc[0][4] = fmaf(a.x, b1.x, acc[0][4]);
                acc[0][5] = fmaf(a.x, b1.y, acc[0][5]);
                acc[0][6] = fmaf(a.x, b1.z, acc[0][6]);
                acc[0][7] = fmaf(a.x, b1.w, acc[0][7]);
                acc[1][0] = fmaf(a.y, b0.x, acc[1][0]);
                acc[1][1] = fmaf(a.y, b0.y, acc[1][1]);
                acc[1][2] = fmaf(a.y, b0.z, acc[1][2]);
                acc[1][3] = fmaf(a.y, b0.w, acc[1][3]);
                acc[1][4] = fmaf(a.y, b1.x, acc[1][4]);
                acc[1][5] = fmaf(a.y, b1.y, acc[1][5]);
                acc[1][6] = fmaf(a.y, b1.z, acc[1][6]);
                acc[1][7] = fmaf(a.y, b1.w, acc[1][7]);
                acc[2][0] = fmaf(a.z, b0.x, acc[2][0]);
                acc[2][1] = fmaf(a.z, b0.y, acc[2][1]);
                acc[2][2] = fmaf(a.z, b0.z, acc[2][2]);
                acc[2][3] = fmaf(a.z, b0.w, acc[2][3]);
                acc[2][4] = fmaf(a.z, b1.x, acc[2][4]);
                acc[2][5] = fmaf(a.z, b1.y, acc[2][5]);
                acc[2][6] = fmaf(a.z, b1.z, acc[2][6]);
                acc[2][7] = fmaf(a.z, b1.w, acc[2][7]);
                acc[3][0] = fmaf(a.w, b0.x, acc[3][0]);
                acc[3][1] = fmaf(a.w, b0.y, acc[3][1]);
                acc[3][2] = fmaf(a.w, b0.z, acc[3][2]);
                acc[3][3] = fmaf(a.w, b0.w, acc[3][3]);
                acc[3][4] = fmaf(a.w, b1.x, acc[3][4]);
                acc[3][5] = fmaf(a.w, b1.y, acc[3][5]);
                acc[3][6] = fmaf(a.w, b1.z, acc[3][6]);
                acc[3][7] = fmaf(a.w, b1.w, acc[3][7]);
            }
            __syncthreads();
        }
    }

    // Epilogue: BatchNorm (eval) + SiLU, vectorized float4 stores
#pragma unroll
    for (int j = 0; j < 4; j++) {
        int c2 = tc * 4 + j;
        float sc = bng[c2] * rsqrtf(bnv[c2] + 1e-5f);
        float sh = bnb[c2] - bnm[c2] * sc;
        float* orow = out + ((size_t)b * C2 + c2) * P_ + p0 + tp * 8;
        float4 o0, o1;
        {
            float v;
            v = acc[j][0] * sc + sh; o0.x = v / (1.f + expf(-v));
            v = acc[j][1] * sc + sh; o0.y = v / (1.f + expf(-v));
            v = acc[j][2] * sc + sh; o0.z = v / (1.f + expf(-v));
            v = acc[j][3] * sc + sh; o0.w = v / (1.f + expf(-v));
            v = acc[j][4] * sc + sh; o1.x = v / (1.f + expf(-v));
            v = acc[j][5] * sc + sh; o1.y = v / (1.f + expf(-v));
            v = acc[j][6] * sc + sh; o1.z = v / (1.f + expf(-v));
            v = acc[j][7] * sc + sh; o1.w = v / (1.f + expf(-v));
        }
        *(float4*)(orow)     = o0;
        *(float4*)(orow + 4) = o1;
    }
}

// ---------------------------------------------------------------------------
extern "C" void kernel_launch(void* const* d_in, const int* in_sizes, int n_in,
                              void* d_out, int out_size) {
    const float* x   = (const float*)d_in[0];
    const float* pw  = (const float*)d_in[1];
    const float* pb  = (const float*)d_in[2];
    const float* cw  = (const float*)d_in[3];
    const float* bng = (const float*)d_in[4];
    const float* bnb = (const float*)d_in[5];
    const float* bnm = (const float*)d_in[6];
    const float* bnv = (const float*)d_in[7];
    float* out = (float*)d_out;

    wt_kernel<<<(KTOT * C2 + 255) / 256, 256>>>(cw);
    offset_kernel<<<B_ * P_ / 256, 256>>>(x, pw, pb);
    dim3 g2(P_ / TPIX, B_);
    main_kernel<<<g2, 512>>>(x, bng, bnb, bnm, bnv, out);
}

// round 4
// speedup vs baseline: 2.0734x; 2.0734x over previous
#include <cuda_runtime.h>
#include <cuda_bf16.h>
#include <math.h>
#include <stdint.h>

#define B_   8
#define C1   128
#define C2   256
#define H_   80
#define W_   80
#define P_   6400
#define NPT  5

#define TPIX   128
#define KCH    64
#define NCHUNK 10

// row pitch: 72 bf16 = 144 bytes (conflict-free for ldmatrix & STS.128)
#define APITCH 144
#define BPITCH 144
#define OPITCH 132          // fp32 elements

// ---------------- device scratch (no runtime allocation allowed) -----------
__device__ int4   g_idx[B_ * NPT * P_];
__device__ float4 g_gw [B_ * NPT * P_];
__device__ unsigned short g_wbh[NCHUNK * C2 * KCH];  // weight hi plane [chunk][c2][64]
__device__ unsigned short g_wbl[NCHUNK * C2 * KCH];  // weight lo plane
__device__ float  g_pwT[C1 * 9 * 12];                // offset weights [c][tt][j pad12]

__device__ __forceinline__ uint32_t smem_u32(const void* p) {
    uint32_t a;
    asm("{ .reg .u64 t; cvta.to.shared.u64 t, %1; cvt.u32.u64 %0, t; }" : "=r"(a) : "l"(p));
    return a;
}

// r = {lo = bf16(a), hi = bf16(b)}
#define CVT2(r, a, b) asm("cvt.rn.bf16x2.f32 %0, %1, %2;" : "=r"(r) : "f"(b), "f"(a))

__device__ __forceinline__ void ldsm4(uint32_t* r, uint32_t addr) {
    asm volatile("ldmatrix.sync.aligned.m8n8.x4.shared.b16 {%0,%1,%2,%3}, [%4];"
        : "=r"(r[0]), "=r"(r[1]), "=r"(r[2]), "=r"(r[3]) : "r"(addr));
}

__device__ __forceinline__ void mma16816(float* d, const uint32_t* a, const uint32_t* b) {
    asm volatile("mma.sync.aligned.m16n8k16.row.col.f32.bf16.bf16.f32 "
        "{%0,%1,%2,%3}, {%4,%5,%6,%7}, {%8,%9}, {%0,%1,%2,%3};"
        : "+f"(d[0]), "+f"(d[1]), "+f"(d[2]), "+f"(d[3])
        : "r"(a[0]), "r"(a[1]), "r"(a[2]), "r"(a[3]), "r"(b[0]), "r"(b[1]));
}

// SMEM layout (bytes)
#define SM_IDX  0
#define SM_GW   10240
#define SM_BN   20480
#define SM_AH   22528
#define SM_AL   (SM_AH + TPIX * APITCH)          // +18432
#define SM_BH   (SM_AL + TPIX * APITCH)          // 59392
#define SM_BL   (SM_BH + C2 * BPITCH)            // +36864
#define SM_O    SM_BH                            // epilogue overlay (67584 B)
#define SM_TOTAL (SM_BL + C2 * BPITCH)           // 133120

// ---------------------------------------------------------------------------
// prep: split conv weights into bf16 hi/lo planes [chunk][c2][64];
// transpose offset-conv weights into [c][tt][j pad 12]
// ---------------------------------------------------------------------------
__global__ void prep_kernel(const float* __restrict__ cw, const float* __restrict__ pw) {
    int e = blockIdx.x * 256 + threadIdx.x;
    if (e < NCHUNK * C2 * KCH) {
        int c   = e >> 14;          // chunk
        int r   = e & 16383;
        int n   = r >> 6;           // c2
        int kk  = r & 63;
        int kpt = c >> 1;
        int c1  = (c & 1) * KCH + kk;
        float v = cw[(n * C1 + c1) * NPT + kpt];
        __nv_bfloat16 h = __float2bfloat16(v);
        float hf = __bfloat162float(h);
        __nv_bfloat16 l = __float2bfloat16(v - hf);
        g_wbh[e] = __bfloat16_as_ushort(h);
        g_wbl[e] = __bfloat16_as_ushort(l);
    }
    if (e < C1 * 9 * 12) {
        int j  = e % 12;
        int ct = e / 12;
        int c  = ct / 9;
        int tt = ct % 9;
        g_pwT[e] = (j < 10) ? pw[(j * C1 + c) * 9 + tt] : 0.f;
    }
}

// ---------------------------------------------------------------------------
// offset conv (3x3, pad 1) + bilinear sampling parameters
// ---------------------------------------------------------------------------
__global__ __launch_bounds__(256)
void offset_kernel(const float* __restrict__ x, const float* __restrict__ pb) {
    extern __shared__ float sw[];                 // 128*9*12 floats = 55296 B
    int t = threadIdx.x;
    for (int i = t; i < C1 * 9 * 12; i += 256) sw[i] = g_pwT[i];
    __syncthreads();

    int tid = blockIdx.x * 256 + t;
    int b = tid / P_, p = tid % P_, h = p / W_, w = p % W_;

    float acc[10];
#pragma unroll
    for (int j = 0; j < 10; j++) acc[j] = pb[j];

    int off[9]; bool ok[9];
#pragma unroll
    for (int tt = 0; tt < 9; tt++) {
        int dh = tt / 3 - 1, dw = tt % 3 - 1;
        int hh = h + dh, ww = w + dw;
        ok[tt]  = (hh >= 0) && (hh < H_) && (ww >= 0) && (ww < W_);
        off[tt] = hh * W_ + ww;
    }

    const float* xb = x + (size_t)b * C1 * P_;
    for (int c = 0; c < C1; c++) {
        const float* xc = xb + c * P_;
        float v[9];
#pragma unroll
        for (int tt = 0; tt < 9; tt++) v[tt] = ok[tt] ? __ldg(xc + off[tt]) : 0.f;
        const float* wc = sw + c * 108;
#pragma unroll
        for (int tt = 0; tt < 9; tt++) {
            float4 w0 = *(const float4*)(wc + tt * 12);
            float4 w1 = *(const float4*)(wc + tt * 12 + 4);
            float2 w2 = *(const float2*)(wc + tt * 12 + 8);
            float xv = v[tt];
            acc[0] = fmaf(xv, w0.x, acc[0]); acc[1] = fmaf(xv, w0.y, acc[1]);
            acc[2] = fmaf(xv, w0.z, acc[2]); acc[3] = fmaf(xv, w0.w, acc[3]);
            acc[4] = fmaf(xv, w1.x, acc[4]); acc[5] = fmaf(xv, w1.y, acc[5]);
            acc[6] = fmaf(xv, w1.z, acc[6]); acc[7] = fmaf(xv, w1.w, acc[7]);
            acc[8] = fmaf(xv, w2.x, acc[8]); acc[9] = fmaf(xv, w2.y, acc[9]);
        }
    }

    const float pnx[NPT] = {0.f, 0.f, 1.f, 1.f, 2.f};
    const float pny[NPT] = {0.f, 1.f, 0.f, 1.f, 0.f};

#pragma unroll
    for (int k = 0; k < NPT; k++) {
        float px = acc[k]       + (float)h + pnx[k];
        float py = acc[NPT + k] + (float)w + pny[k];
        float pf = floorf(px), qf = floorf(py);
        float xl = fminf(fmaxf(pf,       0.f), (float)(H_ - 1));
        float yl = fminf(fmaxf(qf,       0.f), (float)(W_ - 1));
        float xr = fminf(fmaxf(pf + 1.f, 0.f), (float)(H_ - 1));
        float yr = fminf(fmaxf(qf + 1.f, 0.f), (float)(W_ - 1));
        float pxc = fminf(fmaxf(px, 0.f), (float)(H_ - 1));
        float pyc = fminf(fmaxf(py, 0.f), (float)(W_ - 1));
        float ax = 1.f + xl - pxc;
        float bx = 1.f - xr + pxc;
        float ay = 1.f + yl - pyc;
        float by = 1.f - yr + pyc;
        int ixl = (int)xl, iyl = (int)yl, ixr = (int)xr, iyr = (int)yr;
        int gi = (b * NPT + k) * P_ + p;
        g_idx[gi] = make_int4(ixl * W_ + iyl, ixr * W_ + iyr,
                              ixl * W_ + iyr, ixr * W_ + iyl);
        g_gw[gi]  = make_float4(ax * ay, bx * by, ax * by, bx * ay);
    }
}

// ---------------------------------------------------------------------------
// main: fused bilinear gather -> bf16 hi/lo -> mma.sync GEMM -> BN+SiLU
// CTA: 128 pixels x 256 c2, 512 threads (16 warps, 4x4), warp tile 32x64.
// ---------------------------------------------------------------------------
__global__ __launch_bounds__(512, 1)
void main_kernel(const float* __restrict__ x,
                 const float* __restrict__ bng, const float* __restrict__ bnb,
                 const float* __restrict__ bnm, const float* __restrict__ bnv,
                 float* __restrict__ out) {
    extern __shared__ char smem[];
    uint32_t sb = smem_u32(smem);
    int t = threadIdx.x, wid = t >> 5, lid = t & 31;
    int b = blockIdx.y;
    int p0 = blockIdx.x * TPIX;

    // stage bilinear params + BN constants
    for (int i = t; i < NPT * TPIX; i += 512) {
        int kpt = i >> 7, pp = i & 127;
        int gi = (b * NPT + kpt) * P_ + p0 + pp;
        ((int4*)(smem + SM_IDX))[i]  = g_idx[gi];
        ((float4*)(smem + SM_GW))[i] = g_gw[gi];
    }
    if (t < 256) {
        float sc = bng[t] * rsqrtf(bnv[t] + 1e-5f);
        ((float*)(smem + SM_BN))[t]       = sc;
        ((float*)(smem + SM_BN))[256 + t] = bnb[t] - bnm[t] * sc;
    }
    __syncthreads();

    int pix = t & 127;          // gather: pixel
    int kg  = t >> 7;           // gather: 16-c1 group (0..3)
    int wm  = wid & 3;          // warp row group (32 pixels)
    int wn  = wid >> 2;         // warp col group (64 c2)
    const float* xb = x + (size_t)b * C1 * P_;

    float acc[2][8][4];
#pragma unroll
    for (int mt = 0; mt < 2; mt++)
#pragma unroll
        for (int nt = 0; nt < 8; nt++)
#pragma unroll
            for (int j = 0; j < 4; j++) acc[mt][nt][j] = 0.f;

    // ldmatrix base addresses
    uint32_t aAh = sb + SM_AH + (wm * 32 + (lid & 15)) * APITCH + (lid >> 4) * 16;
    uint32_t aAl = aAh + (SM_AL - SM_AH);
    uint32_t aB  = sb + SM_BH + (wn * 64 + (lid & 7) + (lid >> 4) * 8) * BPITCH
                 + ((lid >> 3) & 1) * 16;

    for (int c = 0; c < NCHUNK; c++) {
        int kpt = c >> 1, c1b = (c & 1) * KCH;

        // ---- stage B tiles (linear copy into padded rows) ----
        {
            const uint4* srch = (const uint4*)(g_wbh + c * C2 * KCH);
            const uint4* srcl = (const uint4*)(g_wbl + c * C2 * KCH);
#pragma unroll
            for (int i = 0; i < 4; i++) {
                int u  = i * 512 + t;          // 16B unit: c2 = u>>3, k8 = u&7
                uint32_t d = (u >> 3) * BPITCH + (u & 7) * 16;
                *(uint4*)(smem + SM_BH + d) = __ldg(srch + u);
                *(uint4*)(smem + SM_BL + d) = __ldg(srcl + u);
            }
        }

        // ---- build A tile: one pixel, 16 consecutive c1 per thread ----
        {
            int4   id = ((const int4*)(smem + SM_IDX))[kpt * 128 + pix];
            float4 gw = ((const float4*)(smem + SM_GW))[kpt * 128 + pix];
            unsigned hp[8], lp[8];
            const float* xc = xb + (size_t)(c1b + kg * 16) * P_;
#pragma unroll
            for (int i = 0; i < 8; i++) {
                const float* x0 = xc + (size_t)(2 * i) * P_;
                const float* x1 = x0 + P_;
                float v0 = gw.x * __ldg(x0 + id.x) + gw.y * __ldg(x0 + id.y)
                         + gw.z * __ldg(x0 + id.z) + gw.w * __ldg(x0 + id.w);
                float v1 = gw.x * __ldg(x1 + id.x) + gw.y * __ldg(x1 + id.y)
                         + gw.z * __ldg(x1 + id.z) + gw.w * __ldg(x1 + id.w);
                unsigned h; CVT2(h, v0, v1);
                float h0 = __uint_as_float(h << 16);
                float h1 = __uint_as_float(h & 0xffff0000u);
                unsigned l; CVT2(l, v0 - h0, v1 - h1);
                hp[i] = h; lp[i] = l;
            }
            uint32_t d = (uint32_t)pix * APITCH + kg * 32;
            *(uint4*)(smem + SM_AH + d)      = make_uint4(hp[0], hp[1], hp[2], hp[3]);
            *(uint4*)(smem + SM_AH + d + 16) = make_uint4(hp[4], hp[5], hp[6], hp[7]);
            *(uint4*)(smem + SM_AL + d)      = make_uint4(lp[0], lp[1], lp[2], lp[3]);
            *(uint4*)(smem + SM_AL + d + 16) = make_uint4(lp[4], lp[5], lp[6], lp[7]);
        }
        __syncthreads();

        // ---- compute: 4 k16 steps ----
#pragma unroll
        for (int ks = 0; ks < 4; ks++) {
            uint32_t ah[2][4], al[2][4];
            ldsm4(ah[0], aAh + ks * 32);
            ldsm4(ah[1], aAh + 16 * APITCH + ks * 32);
            ldsm4(al[0], aAl + ks * 32);
            ldsm4(al[1], aAl + 16 * APITCH + ks * 32);
#pragma unroll
            for (int g = 0; g < 4; g++) {        // n-tiles 2g, 2g+1
                uint32_t bh[4], bl[4];
                uint32_t ab = aB + g * 16 * BPITCH + ks * 32;
                ldsm4(bh, ab);
                ldsm4(bl, ab + (SM_BL - SM_BH));
#pragma unroll
                for (int mt = 0; mt < 2; mt++) {
                    mma16816(acc[mt][2 * g],     ah[mt], bh);
                    mma16816(acc[mt][2 * g],     al[mt], bh);
                    mma16816(acc[mt][2 * g],     ah[mt], bl);
                    mma16816(acc[mt][2 * g + 1], ah[mt], bh + 2);
                    mma16816(acc[mt][2 * g + 1], al[mt], bh + 2);
                    mma16816(acc[mt][2 * g + 1], ah[mt], bl + 2);
                }
            }
        }
        __syncthreads();
    }

    // ---- epilogue: two halves of c2 through SMEM, BN + SiLU, coalesced out ----
    const float* scs = (const float*)(smem + SM_BN);
    const float* shs = scs + 256;
    float* sO = (float*)(smem + SM_O);
#pragma unroll
    for (int half = 0; half < 2; half++) {
        if ((wn >> 1) == half) {
#pragma unroll
            for (int mt = 0; mt < 2; mt++)
#pragma unroll
                for (int nt = 0; nt < 8; nt++)
#pragma unroll
                    for (int j = 0; j < 4; j++) {
                        int row = wm * 32 + mt * 16 + (lid >> 2) + 8 * (j >> 1);
                        int col = (wn & 1) * 64 + nt * 8 + 2 * (lid & 3) + (j & 1);
                        sO[col * OPITCH + row] = acc[mt][nt][j];
                    }
        }
        __syncthreads();
#pragma unroll
        for (int it = 0; it < 32; it++) {
            int idx = it * 512 + t;
            int c2l = idx >> 7, pp = idx & 127;
            int c2 = half * 128 + c2l;
            float v = sO[c2l * OPITCH + pp] * scs[c2] + shs[c2];
            out[((size_t)b * C2 + c2) * P_ + p0 + pp] = v / (1.f + __expf(-v));
        }
        __syncthreads();
    }
}

// ---------------------------------------------------------------------------
extern "C" void kernel_launch(void* const* d_in, const int* in_sizes, int n_in,
                              void* d_out, int out_size) {
    const float* x   = (const float*)d_in[0];
    const float* pw  = (const float*)d_in[1];
    const float* pb  = (const float*)d_in[2];
    const float* cw  = (const float*)d_in[3];
    const float* bng = (const float*)d_in[4];
    const float* bnb = (const float*)d_in[5];
    const float* bnm = (const float*)d_in[6];
    const float* bnv = (const float*)d_in[7];
    float* out = (float*)d_out;

    cudaFuncSetAttribute(offset_kernel, cudaFuncAttributeMaxDynamicSharedMemorySize, 55296);
    cudaFuncSetAttribute(main_kernel,   cudaFuncAttributeMaxDynamicSharedMemorySize, SM_TOTAL);

    prep_kernel<<<(NCHUNK * C2 * KCH + 255) / 256, 256>>>(cw, pw);
    offset_kernel<<<B_ * P_ / 256, 256, 55296>>>(x, pb);
    dim3 g2(P_ / TPIX, B_);
    main_kernel<<<g2, 512, SM_TOTAL>>>(x, bng, bnb, bnm, bnv, out);
}

// round 5
// speedup vs baseline: 2.3039x; 1.1112x over previous
#include <cuda_runtime.h>
#include <cuda_bf16.h>
#include <cuda_fp16.h>
#include <math.h>
#include <stdint.h>

#define B_   8
#define C1   128
#define C2   256
#define H_   80
#define W_   80
#define P_   6400
#define NPT  5

#define TPIX   128
#define KCH    64
#define NCHUNK 10

#define APITCH 144          // bytes per A row (64 fp16 = 128B + 16 pad)
#define BPITCH 144          // bytes per B row
#define OPITCH 132          // fp32 elements

// ---------------- device scratch ----------------
__device__ int4   g_idx[B_ * NPT * P_];
__device__ float4 g_gw [B_ * NPT * P_];
__device__ unsigned short g_wh[NCHUNK * C2 * KCH];   // fp16 weights [chunk][c2][64]
__device__ float  g_pwT[C1 * 9 * 12];                // offset weights [c][tt][j pad12]

__device__ __forceinline__ uint32_t smem_u32(const void* p) {
    uint32_t a;
    asm("{ .reg .u64 t; cvta.to.shared.u64 t, %1; cvt.u32.u64 %0, t; }" : "=r"(a) : "l"(p));
    return a;
}

// r = {lo = f16(a), hi = f16(b)}
#define CVT2H(r, a, b) asm("cvt.rn.f16x2.f32 %0, %1, %2;" : "=r"(r) : "f"(b), "f"(a))

__device__ __forceinline__ void ldsm4(uint32_t* r, uint32_t addr) {
    asm volatile("ldmatrix.sync.aligned.m8n8.x4.shared.b16 {%0,%1,%2,%3}, [%4];"
        : "=r"(r[0]), "=r"(r[1]), "=r"(r[2]), "=r"(r[3]) : "r"(addr));
}

__device__ __forceinline__ void mma16816(float* d, const uint32_t* a, const uint32_t* b) {
    asm volatile("mma.sync.aligned.m16n8k16.row.col.f32.f16.f16.f32 "
        "{%0,%1,%2,%3}, {%4,%5,%6,%7}, {%8,%9}, {%0,%1,%2,%3};"
        : "+f"(d[0]), "+f"(d[1]), "+f"(d[2]), "+f"(d[3])
        : "r"(a[0]), "r"(a[1]), "r"(a[2]), "r"(a[3]), "r"(b[0]), "r"(b[1]));
}

// SMEM layout (bytes): BN | stage0 {Ah, Al, B} | stage1 {Ah, Al, B}
#define SM_BN    0
#define SM_ST    2048
#define A_BYTES  (TPIX * APITCH)        // 18432
#define B_BYTES  (C2 * BPITCH)          // 36864
#define STG      (2 * A_BYTES + B_BYTES) // 73728
#define SM_TOTAL (SM_ST + 2 * STG)      // 149504

// ---------------------------------------------------------------------------
__global__ void prep_kernel(const float* __restrict__ cw, const float* __restrict__ pw) {
    int e = blockIdx.x * 256 + threadIdx.x;
    if (e < NCHUNK * C2 * KCH) {
        int c   = e >> 14;
        int r   = e & 16383;
        int n   = r >> 6;
        int kk  = r & 63;
        int kpt = c >> 1;
        int c1  = (c & 1) * KCH + kk;
        float v = cw[(n * C1 + c1) * NPT + kpt];
        g_wh[e] = __half_as_ushort(__float2half(v));
    }
    if (e < C1 * 9 * 12) {
        int j  = e % 12;
        int ct = e / 12;
        int c  = ct / 9;
        int tt = ct % 9;
        g_pwT[e] = (j < 10) ? pw[(j * C1 + c) * 9 + tt] : 0.f;
    }
}

// ---------------------------------------------------------------------------
__global__ __launch_bounds__(256)
void offset_kernel(const float* __restrict__ x, const float* __restrict__ pb) {
    extern __shared__ float sw[];
    int t = threadIdx.x;
    for (int i = t; i < C1 * 9 * 12; i += 256) sw[i] = g_pwT[i];
    __syncthreads();

    int tid = blockIdx.x * 256 + t;
    int b = tid / P_, p = tid % P_, h = p / W_, w = p % W_;

    float acc[10];
#pragma unroll
    for (int j = 0; j < 10; j++) acc[j] = pb[j];

    int off[9]; bool ok[9];
#pragma unroll
    for (int tt = 0; tt < 9; tt++) {
        int dh = tt / 3 - 1, dw = tt % 3 - 1;
        int hh = h + dh, ww = w + dw;
        ok[tt]  = (hh >= 0) && (hh < H_) && (ww >= 0) && (ww < W_);
        off[tt] = hh * W_ + ww;
    }

    const float* xb = x + (size_t)b * C1 * P_;
    for (int c = 0; c < C1; c++) {
        const float* xc = xb + c * P_;
        float v[9];
#pragma unroll
        for (int tt = 0; tt < 9; tt++) v[tt] = ok[tt] ? __ldg(xc + off[tt]) : 0.f;
        const float* wc = sw + c * 108;
#pragma unroll
        for (int tt = 0; tt < 9; tt++) {
            float4 w0 = *(const float4*)(wc + tt * 12);
            float4 w1 = *(const float4*)(wc + tt * 12 + 4);
            float2 w2 = *(const float2*)(wc + tt * 12 + 8);
            float xv = v[tt];
            acc[0] = fmaf(xv, w0.x, acc[0]); acc[1] = fmaf(xv, w0.y, acc[1]);
            acc[2] = fmaf(xv, w0.z, acc[2]); acc[3] = fmaf(xv, w0.w, acc[3]);
            acc[4] = fmaf(xv, w1.x, acc[4]); acc[5] = fmaf(xv, w1.y, acc[5]);
            acc[6] = fmaf(xv, w1.z, acc[6]); acc[7] = fmaf(xv, w1.w, acc[7]);
            acc[8] = fmaf(xv, w2.x, acc[8]); acc[9] = fmaf(xv, w2.y, acc[9]);
        }
    }

    const float pnx[NPT] = {0.f, 0.f, 1.f, 1.f, 2.f};
    const float pny[NPT] = {0.f, 1.f, 0.f, 1.f, 0.f};

#pragma unroll
    for (int k = 0; k < NPT; k++) {
        float px = acc[k]       + (float)h + pnx[k];
        float py = acc[NPT + k] + (float)w + pny[k];
        float pf = floorf(px), qf = floorf(py);
        float xl = fminf(fmaxf(pf,       0.f), (float)(H_ - 1));
        float yl = fminf(fmaxf(qf,       0.f), (float)(W_ - 1));
        float xr = fminf(fmaxf(pf + 1.f, 0.f), (float)(H_ - 1));
        float yr = fminf(fmaxf(qf + 1.f, 0.f), (float)(W_ - 1));
        float pxc = fminf(fmaxf(px, 0.f), (float)(H_ - 1));
        float pyc = fminf(fmaxf(py, 0.f), (float)(W_ - 1));
        float ax = 1.f + xl - pxc;
        float bx = 1.f - xr + pxc;
        float ay = 1.f + yl - pyc;
        float by = 1.f - yr + pyc;
        int ixl = (int)xl, iyl = (int)yl, ixr = (int)xr, iyr = (int)yr;
        int gi = (b * NPT + k) * P_ + p;
        g_idx[gi] = make_int4(ixl * W_ + iyl, ixr * W_ + iyr,
                              ixl * W_ + iyr, ixr * W_ + iyl);
        g_gw[gi]  = make_float4(ax * ay, bx * by, ax * by, bx * ay);
    }
}

// ---------------------------------------------------------------------------
// main: pipelined gather (fp16 hi/lo A, fp16 B) + mma.sync + BN/SiLU
// CTA 128 pixels x 256 c2, 512 threads, double-buffered K chunks of 64.
// ---------------------------------------------------------------------------
__global__ __launch_bounds__(512, 1)
void main_kernel(const float* __restrict__ x,
                 const float* __restrict__ bng, const float* __restrict__ bnb,
                 const float* __restrict__ bnm, const float* __restrict__ bnv,
                 float* __restrict__ out) {
    extern __shared__ char smem[];
    uint32_t sb = smem_u32(smem);
    int t = threadIdx.x, wid = t >> 5, lid = t & 31;
    int b = blockIdx.y;
    int p0 = blockIdx.x * TPIX;

    if (t < 256) {
        float sc = bng[t] * rsqrtf(bnv[t] + 1e-5f);
        ((float*)(smem + SM_BN))[t]       = sc;
        ((float*)(smem + SM_BN))[256 + t] = bnb[t] - bnm[t] * sc;
    }

    int pix = t & 127;          // gather: pixel
    int kg  = t >> 7;           // gather: 16-c1 group (0..3)
    int wm  = wid & 3;
    int wn  = wid >> 2;
    const float* xb = x + (size_t)b * C1 * P_;

    float acc[2][8][4];
#pragma unroll
    for (int mt = 0; mt < 2; mt++)
#pragma unroll
        for (int nt = 0; nt < 8; nt++)
#pragma unroll
            for (int j = 0; j < 4; j++) acc[mt][nt][j] = 0.f;

    // ---- prologue: stage chunk 0 into stage 0 ----
    {
        const uint4* src = (const uint4*)g_wh;
#pragma unroll
        for (int i = 0; i < 4; i++) {
            int u = i * 512 + t;
            *(uint4*)(smem + SM_ST + 2 * A_BYTES + (u >> 3) * BPITCH + (u & 7) * 16) =
                __ldg(src + u);
        }
        int gi = b * NPT * P_ + p0 + pix;
        int4   id  = __ldg(&g_idx[gi]);
        float4 gwv = __ldg(&g_gw[gi]);
        const float* xc = xb + (size_t)(kg * 16) * P_;
#pragma unroll
        for (int i = 0; i < 8; i++) {
            const float* x0 = xc + (size_t)(2 * i) * P_;
            const float* x1 = x0 + P_;
            float v0 = gwv.x * __ldg(x0 + id.x) + gwv.y * __ldg(x0 + id.y)
                     + gwv.z * __ldg(x0 + id.z) + gwv.w * __ldg(x0 + id.w);
            float v1 = gwv.x * __ldg(x1 + id.x) + gwv.y * __ldg(x1 + id.y)
                     + gwv.z * __ldg(x1 + id.z) + gwv.w * __ldg(x1 + id.w);
            unsigned h; CVT2H(h, v0, v1);
            float h0 = __half2float(__ushort_as_half((unsigned short)(h & 0xffff)));
            float h1 = __half2float(__ushort_as_half((unsigned short)(h >> 16)));
            unsigned l; CVT2H(l, v0 - h0, v1 - h1);
            uint32_t d = (uint32_t)pix * APITCH + kg * 32 + i * 4;
            *(unsigned*)(smem + SM_ST + d)           = h;
            *(unsigned*)(smem + SM_ST + A_BYTES + d) = l;
        }
    }
    __syncthreads();

#pragma unroll 1
    for (int c = 0; c < NCHUNK; c++) {
        int st = c & 1;
        uint32_t sAh = sb + SM_ST + st * STG;
        uint32_t sBB = sAh + 2 * A_BYTES;
        uint32_t nA  = SM_ST + (st ^ 1) * STG;      // byte offsets into smem[]
        bool pf = (c < NCHUNK - 1);
        int cn = c + 1;

        // prefetch next B tile + bilinear params
        uint4 breg[4];
        int4 id; float4 gwv;
        const float* xc = xb;
        if (pf) {
            const uint4* src = (const uint4*)(g_wh + cn * C2 * KCH);
#pragma unroll
            for (int i = 0; i < 4; i++) breg[i] = __ldg(src + i * 512 + t);
            int gi = (b * NPT + (cn >> 1)) * P_ + p0 + pix;
            id  = __ldg(&g_idx[gi]);
            gwv = __ldg(&g_gw[gi]);
            xc = xb + (size_t)((cn & 1) * KCH + kg * 16) * P_;
        }

        uint32_t aAh = sAh + (wm * 32 + (lid & 15)) * APITCH + (lid >> 4) * 16;
        uint32_t aAl = aAh + A_BYTES;
        uint32_t aB  = sBB + (wn * 64 + (lid & 7) + (lid >> 4) * 8) * BPITCH
                     + ((lid >> 3) & 1) * 16;
        uint32_t dA  = nA + (uint32_t)pix * APITCH + kg * 32;

        uint32_t ah[2][4], al[2][4];
#pragma unroll
        for (int s = 0; s < 8; s++) {
            int ks = s >> 1, gp = s & 1;

            // issue next-chunk corner loads (2 samples) early
            float c00, c01, c02, c03, c10, c11, c12, c13;
            if (pf) {
                const float* x0 = xc + (size_t)(2 * s) * P_;
                const float* x1 = x0 + P_;
                c00 = __ldg(x0 + id.x); c01 = __ldg(x0 + id.y);
                c02 = __ldg(x0 + id.z); c03 = __ldg(x0 + id.w);
                c10 = __ldg(x1 + id.x); c11 = __ldg(x1 + id.y);
                c12 = __ldg(x1 + id.z); c13 = __ldg(x1 + id.w);
            }

            if (gp == 0) {
                ldsm4(ah[0], aAh + ks * 32);
                ldsm4(ah[1], aAh + 16 * APITCH + ks * 32);
                ldsm4(al[0], aAl + ks * 32);
                ldsm4(al[1], aAl + 16 * APITCH + ks * 32);
            }

#pragma unroll
            for (int g2 = 0; g2 < 2; g2++) {
                int g = gp * 2 + g2;
                uint32_t bf[4];
                ldsm4(bf, aB + g * 16 * BPITCH + ks * 32);
#pragma unroll
                for (int mt = 0; mt < 2; mt++) {
                    mma16816(acc[mt][2 * g],     ah[mt], bf);
                    mma16816(acc[mt][2 * g],     al[mt], bf);
                    mma16816(acc[mt][2 * g + 1], ah[mt], bf + 2);
                    mma16816(acc[mt][2 * g + 1], al[mt], bf + 2);
                }
            }

            // combine + convert + store the 2 samples
            if (pf) {
                float v0 = gwv.x * c00 + gwv.y * c01 + gwv.z * c02 + gwv.w * c03;
                float v1 = gwv.x * c10 + gwv.y * c11 + gwv.z * c12 + gwv.w * c13;
                unsigned h; CVT2H(h, v0, v1);
                float h0 = __half2float(__ushort_as_half((unsigned short)(h & 0xffff)));
                float h1 = __half2float(__ushort_as_half((unsigned short)(h >> 16)));
                unsigned l; CVT2H(l, v0 - h0, v1 - h1);
                *(unsigned*)(smem + dA + s * 4)           = h;
                *(unsigned*)(smem + dA + A_BYTES + s * 4) = l;
            }
        }

        if (pf) {
#pragma unroll
            for (int i = 0; i < 4; i++) {
                int u = i * 512 + t;
                *(uint4*)(smem + nA + 2 * A_BYTES + (u >> 3) * BPITCH + (u & 7) * 16) =
                    breg[i];
            }
        }
        __syncthreads();
    }

    // ---- epilogue: BN + SiLU via SMEM transpose, coalesced out ----
    const float* scs = (const float*)(smem + SM_BN);
    const float* shs = scs + 256;
    float* sO = (float*)(smem + SM_ST);
#pragma unroll
    for (int half = 0; half < 2; half++) {
        if ((wn >> 1) == half) {
#pragma unroll
            for (int mt = 0; mt < 2; mt++)
#pragma unroll
                for (int nt = 0; nt < 8; nt++)
#pragma unroll
                    for (int j = 0; j < 4; j++) {
                        int row = wm * 32 + mt * 16 + (lid >> 2) + 8 * (j >> 1);
                        int col = (wn & 1) * 64 + nt * 8 + 2 * (lid & 3) + (j & 1);
                        sO[col * OPITCH + row] = acc[mt][nt][j];
                    }
        }
        __syncthreads();
#pragma unroll
        for (int it = 0; it < 32; it++) {
            int idx = it * 512 + t;
            int c2l = idx >> 7, pp = idx & 127;
            int c2 = half * 128 + c2l;
            float v = sO[c2l * OPITCH + pp] * scs[c2] + shs[c2];
            out[((size_t)b * C2 + c2) * P_ + p0 + pp] = v / (1.f + __expf(-v));
        }
        __syncthreads();
    }
}

// ---------------------------------------------------------------------------
extern "C" void kernel_launch(void* const* d_in, const int* in_sizes, int n_in,
                              void* d_out, int out_size) {
    const float* x   = (const float*)d_in[0];
    const float* pw  = (const float*)d_in[1];
    const float* pb  = (const float*)d_in[2];
    const float* cw  = (const float*)d_in[3];
    const float* bng = (const float*)d_in[4];
    const float* bnb = (const float*)d_in[5];
    const float* bnm = (const float*)d_in[6];
    const float* bnv = (const float*)d_in[7];
    float* out = (float*)d_out;

    cudaFuncSetAttribute(offset_kernel, cudaFuncAttributeMaxDynamicSharedMemorySize, 55296);
    cudaFuncSetAttribute(main_kernel,   cudaFuncAttributeMaxDynamicSharedMemorySize, SM_TOTAL);

    prep_kernel<<<(NCHUNK * C2 * KCH + 255) / 256, 256>>>(cw, pw);
    offset_kernel<<<B_ * P_ / 256, 256, 55296>>>(x, pb);
    dim3 g2(P_ / TPIX, B_);
    main_kernel<<<g2, 512, SM_TOTAL>>>(x, bng, bnb, bnm, bnv, out);
}

// round 7
// speedup vs baseline: 2.6490x; 1.1498x over previous
#include <cuda_runtime.h>
#include <cuda_bf16.h>
#include <cuda_fp16.h>
#include <math.h>
#include <stdint.h>

#define B_   8
#define C1   128
#define C2   256
#define H_   80
#define W_   80
#define P_   6400
#define NPT  5

#define TPIX   128
#define KCH    64
#define NCHUNK 10

#define APITCH 144          // bytes per A row (64 fp16 = 128B + 16 pad)
#define BPITCH 144          // bytes per B row
#define OPITCH 132          // fp32 elements

// ---------------- device scratch ----------------
__device__ int4   g_idx[B_ * NPT * P_];
__device__ float4 g_gw [B_ * NPT * P_];
__device__ unsigned short g_wh[NCHUNK * C2 * KCH];   // fp16 weights [chunk][c2][64]
__device__ float  g_pwT[C1 * 9 * 12];                // offset weights [c][tt][j pad12]

__device__ __forceinline__ uint32_t smem_u32(const void* p) {
    uint32_t a;
    asm("{ .reg .u64 t; cvta.to.shared.u64 t, %1; cvt.u32.u64 %0, t; }" : "=r"(a) : "l"(p));
    return a;
}

// r = {lo = f16(a), hi = f16(b)}
#define CVT2H(r, a, b) asm("cvt.rn.f16x2.f32 %0, %1, %2;" : "=r"(r) : "f"(b), "f"(a))

__device__ __forceinline__ void ldsm4(uint32_t* r, uint32_t addr) {
    asm volatile("ldmatrix.sync.aligned.m8n8.x4.shared.b16 {%0,%1,%2,%3}, [%4];"
        : "=r"(r[0]), "=r"(r[1]), "=r"(r[2]), "=r"(r[3]) : "r"(addr));
}

__device__ __forceinline__ void mma16816(float* d, const uint32_t* a, const uint32_t* b) {
    asm volatile("mma.sync.aligned.m16n8k16.row.col.f32.f16.f16.f32 "
        "{%0,%1,%2,%3}, {%4,%5,%6,%7}, {%8,%9}, {%0,%1,%2,%3};"
        : "+f"(d[0]), "+f"(d[1]), "+f"(d[2]), "+f"(d[3])
        : "r"(a[0]), "r"(a[1]), "r"(a[2]), "r"(a[3]), "r"(b[0]), "r"(b[1]));
}

// SMEM layout (bytes): BN | stage0 {A, B} | stage1 {A, B}
#define SM_BN    0
#define SM_ST    2048
#define A_BYTES  (TPIX * APITCH)         // 18432
#define B_BYTES  (C2 * BPITCH)           // 36864
#define STG      (A_BYTES + B_BYTES)     // 55296
#define SM_TOTAL (SM_ST + 2 * STG)       // 112640

// ---------------------------------------------------------------------------
__global__ void prep_kernel(const float* __restrict__ cw, const float* __restrict__ pw) {
    int e = blockIdx.x * 256 + threadIdx.x;
    if (e < NCHUNK * C2 * KCH) {
        int c   = e >> 14;
        int r   = e & 16383;
        int n   = r >> 6;
        int kk  = r & 63;
        int kpt = c >> 1;
        int c1  = (c & 1) * KCH + kk;
        float v = cw[(n * C1 + c1) * NPT + kpt];
        g_wh[e] = __half_as_ushort(__float2half(v));
    }
    if (e < C1 * 9 * 12) {
        int j  = e % 12;
        int ct = e / 12;
        int c  = ct / 9;
        int tt = ct % 9;
        g_pwT[e] = (j < 10) ? pw[(j * C1 + c) * 9 + tt] : 0.f;
    }
}

// ---------------------------------------------------------------------------
__global__ __launch_bounds__(256)
void offset_kernel(const float* __restrict__ x, const float* __restrict__ pb) {
    extern __shared__ float sw[];
    int t = threadIdx.x;
    for (int i = t; i < C1 * 9 * 12; i += 256) sw[i] = g_pwT[i];
    __syncthreads();

    int tid = blockIdx.x * 256 + t;
    int b = tid / P_, p = tid % P_, h = p / W_, w = p % W_;

    float acc[10];
#pragma unroll
    for (int j = 0; j < 10; j++) acc[j] = pb[j];

    int off[9]; bool ok[9];
#pragma unroll
    for (int tt = 0; tt < 9; tt++) {
        int dh = tt / 3 - 1, dw = tt % 3 - 1;
        int hh = h + dh, ww = w + dw;
        ok[tt]  = (hh >= 0) && (hh < H_) && (ww >= 0) && (ww < W_);
        off[tt] = hh * W_ + ww;
    }

    const float* xb = x + (size_t)b * C1 * P_;
    for (int c = 0; c < C1; c++) {
        const float* xc = xb + c * P_;
        float v[9];
#pragma unroll
        for (int tt = 0; tt < 9; tt++) v[tt] = ok[tt] ? __ldg(xc + off[tt]) : 0.f;
        const float* wc = sw + c * 108;
#pragma unroll
        for (int tt = 0; tt < 9; tt++) {
            float4 w0 = *(const float4*)(wc + tt * 12);
            float4 w1 = *(const float4*)(wc + tt * 12 + 4);
            float2 w2 = *(const float2*)(wc + tt * 12 + 8);
            float xv = v[tt];
            acc[0] = fmaf(xv, w0.x, acc[0]); acc[1] = fmaf(xv, w0.y, acc[1]);
            acc[2] = fmaf(xv, w0.z, acc[2]); acc[3] = fmaf(xv, w0.w, acc[3]);
            acc[4] = fmaf(xv, w1.x, acc[4]); acc[5] = fmaf(xv, w1.y, acc[5]);
            acc[6] = fmaf(xv, w1.z, acc[6]); acc[7] = fmaf(xv, w1.w, acc[7]);
            acc[8] = fmaf(xv, w2.x, acc[8]); acc[9] = fmaf(xv, w2.y, acc[9]);
        }
    }

    const float pnx[NPT] = {0.f, 0.f, 1.f, 1.f, 2.f};
    const float pny[NPT] = {0.f, 1.f, 0.f, 1.f, 0.f};

#pragma unroll
    for (int k = 0; k < NPT; k++) {
        float px = acc[k]       + (float)h + pnx[k];
        float py = acc[NPT + k] + (float)w + pny[k];
        float pf = floorf(px), qf = floorf(py);
        float xl = fminf(fmaxf(pf,       0.f), (float)(H_ - 1));
        float yl = fminf(fmaxf(qf,       0.f), (float)(W_ - 1));
        float xr = fminf(fmaxf(pf + 1.f, 0.f), (float)(H_ - 1));
        float yr = fminf(fmaxf(qf + 1.f, 0.f), (float)(W_ - 1));
        float pxc = fminf(fmaxf(px, 0.f), (float)(H_ - 1));
        float pyc = fminf(fmaxf(py, 0.f), (float)(W_ - 1));
        float ax = 1.f + xl - pxc;
        float bx = 1.f - xr + pxc;
        float ay = 1.f + yl - pyc;
        float by = 1.f - yr + pyc;
        int ixl = (int)xl, iyl = (int)yl, ixr = (int)xr, iyr = (int)yr;
        int gi = (b * NPT + k) * P_ + p;
        g_idx[gi] = make_int4(ixl * W_ + iyl, ixr * W_ + iyr,
                              ixl * W_ + iyr, ixr * W_ + iyl);
        g_gw[gi]  = make_float4(ax * ay, bx * by, ax * by, bx * ay);
    }
}

// ---------------------------------------------------------------------------
// main: pipelined gather (single fp16 A plane, fp16 B) + mma.sync + BN/SiLU
// CTA 128 pixels x 256 c2, 512 threads, double-buffered K chunks of 64.
// ---------------------------------------------------------------------------
__global__ __launch_bounds__(512, 1)
void main_kernel(const float* __restrict__ x,
                 const float* __restrict__ bng, const float* __restrict__ bnb,
                 const float* __restrict__ bnm, const float* __restrict__ bnv,
                 float* __restrict__ out) {
    extern __shared__ char smem[];
    uint32_t sb = smem_u32(smem);
    int t = threadIdx.x, wid = t >> 5, lid = t & 31;
    int b = blockIdx.y;
    int p0 = blockIdx.x * TPIX;

    if (t < 256) {
        float sc = bng[t] * rsqrtf(bnv[t] + 1e-5f);
        ((float*)(smem + SM_BN))[t]       = sc;
        ((float*)(smem + SM_BN))[256 + t] = bnb[t] - bnm[t] * sc;
    }

    int pix = t & 127;          // gather: pixel
    int kg  = t >> 7;           // gather: 16-c1 group (0..3)
    int wm  = wid & 3;
    int wn  = wid >> 2;
    const float* xb = x + (size_t)b * C1 * P_;

    float acc[2][8][4];
#pragma unroll
    for (int mt = 0; mt < 2; mt++)
#pragma unroll
        for (int nt = 0; nt < 8; nt++)
#pragma unroll
            for (int j = 0; j < 4; j++) acc[mt][nt][j] = 0.f;

    // ---- prologue: stage chunk 0 into stage 0 ----
    {
        const uint4* src = (const uint4*)g_wh;
#pragma unroll
        for (int i = 0; i < 4; i++) {
            int u = i * 512 + t;
            *(uint4*)(smem + SM_ST + A_BYTES + (u >> 3) * BPITCH + (u & 7) * 16) =
                __ldg(src + u);
        }
        int gi = b * NPT * P_ + p0 + pix;
        int4   id  = __ldg(&g_idx[gi]);
        float4 gwv = __ldg(&g_gw[gi]);
        const float* xc = xb + (size_t)(kg * 16) * P_;
#pragma unroll
        for (int i = 0; i < 8; i++) {
            const float* x0 = xc + (size_t)(2 * i) * P_;
            const float* x1 = x0 + P_;
            float v0 = gwv.x * __ldg(x0 + id.x) + gwv.y * __ldg(x0 + id.y)
                     + gwv.z * __ldg(x0 + id.z) + gwv.w * __ldg(x0 + id.w);
            float v1 = gwv.x * __ldg(x1 + id.x) + gwv.y * __ldg(x1 + id.y)
                     + gwv.z * __ldg(x1 + id.z) + gwv.w * __ldg(x1 + id.w);
            unsigned h; CVT2H(h, v0, v1);
            *(unsigned*)(smem + SM_ST + (uint32_t)pix * APITCH + kg * 32 + i * 4) = h;
        }
    }
    __syncthreads();

#pragma unroll 1
    for (int c = 0; c < NCHUNK; c++) {
        int st = c & 1;
        uint32_t sA  = sb + SM_ST + st * STG;
        uint32_t sBB = sA + A_BYTES;
        uint32_t nA  = SM_ST + (st ^ 1) * STG;      // byte offset into smem[]
        bool pf = (c < NCHUNK - 1);
        int cn = c + 1;

        // prefetch next B tile + bilinear params
        uint4 breg[4];
        int4 id; float4 gwv;
        const float* xc = xb;
        if (pf) {
            const uint4* src = (const uint4*)(g_wh + cn * C2 * KCH);
#pragma unroll
            for (int i = 0; i < 4; i++) breg[i] = __ldg(src + i * 512 + t);
            int gi = (b * NPT + (cn >> 1)) * P_ + p0 + pix;
            id  = __ldg(&g_idx[gi]);
            gwv = __ldg(&g_gw[gi]);
            xc = xb + (size_t)((cn & 1) * KCH + kg * 16) * P_;
        }

        uint32_t aA = sA + (wm * 32 + (lid & 15)) * APITCH + (lid >> 4) * 16;
        uint32_t aB = sBB + (wn * 64 + (lid & 7) + (lid >> 4) * 8) * BPITCH
                    + ((lid >> 3) & 1) * 16;
        uint32_t dA = nA + (uint32_t)pix * APITCH + kg * 32;

        uint32_t ah[2][4];
#pragma unroll
        for (int s = 0; s < 8; s++) {
            int ks = s >> 1, gp = s & 1;

            // issue next-chunk corner loads (2 samples) early
            float c00, c01, c02, c03, c10, c11, c12, c13;
            if (pf) {
                const float* x0 = xc + (size_t)(2 * s) * P_;
                const float* x1 = x0 + P_;
                c00 = __ldg(x0 + id.x); c01 = __ldg(x0 + id.y);
                c02 = __ldg(x0 + id.z); c03 = __ldg(x0 + id.w);
                c10 = __ldg(x1 + id.x); c11 = __ldg(x1 + id.y);
                c12 = __ldg(x1 + id.z); c13 = __ldg(x1 + id.w);
            }

            if (gp == 0) {
                ldsm4(ah[0], aA + ks * 32);
                ldsm4(ah[1], aA + 16 * APITCH + ks * 32);
            }

#pragma unroll
            for (int g2 = 0; g2 < 2; g2++) {
                int g = gp * 2 + g2;
                uint32_t bf[4];
                ldsm4(bf, aB + g * 16 * BPITCH + ks * 32);
#pragma unroll
                for (int mt = 0; mt < 2; mt++) {
                    mma16816(acc[mt][2 * g],     ah[mt], bf);
                    mma16816(acc[mt][2 * g + 1], ah[mt], bf + 2);
                }
            }

            // combine + convert + store the 2 samples
            if (pf) {
                float v0 = gwv.x * c00 + gwv.y * c01 + gwv.z * c02 + gwv.w * c03;
                float v1 = gwv.x * c10 + gwv.y * c11 + gwv.z * c12 + gwv.w * c13;
                unsigned h; CVT2H(h, v0, v1);
                *(unsigned*)(smem + dA + s * 4) = h;
            }
        }

        if (pf) {
#pragma unroll
            for (int i = 0; i < 4; i++) {
                int u = i * 512 + t;
                *(uint4*)(smem + nA + A_BYTES + (u >> 3) * BPITCH + (u & 7) * 16) =
                    breg[i];
            }
        }
        __syncthreads();
    }

    // ---- epilogue: BN + SiLU via SMEM transpose, coalesced out ----
    const float* scs = (const float*)(smem + SM_BN);
    const float* shs = scs + 256;
    float* sO = (float*)(smem + SM_ST);
#pragma unroll
    for (int half = 0; half < 2; half++) {
        if ((wn >> 1) == half) {
#pragma unroll
            for (int mt = 0; mt < 2; mt++)
#pragma unroll
                for (int nt = 0; nt < 8; nt++)
#pragma unroll
                    for (int j = 0; j < 4; j++) {
                        int row = wm * 32 + mt * 16 + (lid >> 2) + 8 * (j >> 1);
                        int col = (wn & 1) * 64 + nt * 8 + 2 * (lid & 3) + (j & 1);
                        sO[col * OPITCH + row] = acc[mt][nt][j];
                    }
        }
        __syncthreads();
#pragma unroll
        for (int it = 0; it < 32; it++) {
            int idx = it * 512 + t;
            int c2l = idx >> 7, pp = idx & 127;
            int c2 = half * 128 + c2l;
            float v = sO[c2l * OPITCH + pp] * scs[c2] + shs[c2];
            out[((size_t)b * C2 + c2) * P_ + p0 + pp] = v / (1.f + __expf(-v));
        }
        __syncthreads();
    }
}

// ---------------------------------------------------------------------------
extern "C" void kernel_launch(void* const* d_in, const int* in_sizes, int n_in,
                              void* d_out, int out_size) {
    const float* x   = (const float*)d_in[0];
    const float* pw  = (const float*)d_in[1];
    const float* pb  = (const float*)d_in[2];
    const float* cw  = (const float*)d_in[3];
    const float* bng = (const float*)d_in[4];
    const float* bnb = (const float*)d_in[5];
    const float* bnm = (const float*)d_in[6];
    const float* bnv = (const float*)d_in[7];
    float* out = (float*)d_out;

    cudaFuncSetAttribute(offset_kernel, cudaFuncAttributeMaxDynamicSharedMemorySize, 55296);
    cudaFuncSetAttribute(main_kernel,   cudaFuncAttributeMaxDynamicSharedMemorySize, SM_TOTAL);

    prep_kernel<<<(NCHUNK * C2 * KCH + 255) / 256, 256>>>(cw, pw);
    offset_kernel<<<B_ * P_ / 256, 256, 55296>>>(x, pb);
    dim3 g2(P_ / TPIX, B_);
    main_kernel<<<g2, 512, SM_TOTAL>>>(x, bng, bnb, bnm, bnv, out);
}